// round 1
// baseline (speedup 1.0000x reference)
#include <cuda_runtime.h>
#include <cstdint>

// ---------------------------------------------------------------------------
// SpinConvSq2dSparse: N=8, Lx=Ly=128, C=16, K=9 (-> 5 effective taps), F_IN=64
//
// Restructured as: per-pixel GEMM  I[4*64px, 48cols] = V @ W  (K=80)
//   rows g=0..2 : V = x1[tap][c][i=g]  weights [s110 | s101 | t]   (shared W_A)
//   rows g=3    : V = x0[tap][c]       weights [a0   | b    | 0 ]  (W_B)
// epilogue: out0[d] = a0 + sum_i s110[d,i]*s[i]
//           out1[d,i] = b[d]*s[i] + s101[d,i] + cross(t[d,:], s)[i]
//   with s = spin permuted (1,2,0); all scalar prefactors folded into W.
// ---------------------------------------------------------------------------

#define TPAD 67      // feat tile row pad (conflict-free for 8-pixel stride loads)
#define NTP  194     // tile pixels: 66 (center row + y halo) + 64 (x-1) + 64 (x+1)
#define IPAD 49      // intermediate row pad
#define SMEM_FLOATS (3840 + 3840 + NTP * TPAD)   // WA + WB + tile = 20678 floats
#define SMEM_BYTES  (SMEM_FLOATS * 4)            // 82712 B

__device__ float g_WA[80 * 48];
__device__ float g_WB[80 * 48];

// ---------------------------------------------------------------------------
// Prep: build effective 5-tap weights with prefactors folded in.
// tap0 = sum of k=0..4 (all center); tap1..4 = k=5..8 -> (x-1),(x+1),(y-1),(y+1)
// ---------------------------------------------------------------------------
__global__ void prep_weights(const float* __restrict__ w000,
                             const float* __restrict__ w011,
                             const float* __restrict__ w101,
                             const float* __restrict__ w110,
                             const float* __restrict__ w111) {
    int idx = blockIdx.x * blockDim.x + threadIdx.x;
    if (idx >= 80 * 48) return;
    int r   = idx / 48;        // (tap, c)
    int col = idx % 48;
    int tap = r / 16;
    int c   = r % 16;
    int cls = col / 16;
    int d   = col % 16;

    const double C0  = 0.28209479177387814;
    const double C1  = 0.4886025119029199;
    const double IS3 = 0.57735026918962576;   // 1/sqrt(3)
    const double IS6 = 0.40824829046386302;   // 1/sqrt(6)
    const double PW0 = 0.058925565098878960;  // sqrt(1/(9*2*16))
    const double PW1 = 1.0 / 12.0;            // sqrt(3/(9*3*16))

    int off = c * 16 + d;
    float s000, s011, s101, s110, s111;
    if (tap == 0) {
        s000 = s011 = s101 = s110 = s111 = 0.f;
        #pragma unroll
        for (int k = 0; k < 5; k++) {
            s000 += w000[k * 256 + off];
            s011 += w011[k * 256 + off];
            s101 += w101[k * 256 + off];
            s110 += w110[k * 256 + off];
            s111 += w111[k * 256 + off];
        }
    } else {
        int k = tap + 4;
        s000 = w000[k * 256 + off];
        s011 = w011[k * 256 + off];
        s101 = w101[k * 256 + off];
        s110 = w110[k * 256 + off];
        s111 = w111[k * 256 + off];
    }

    float a, b;
    if (cls == 0)      { a = (float)(PW0 * IS3 * C1) * s110;  b = (float)(PW0 * C0)       * s000; }
    else if (cls == 1) { a = (float)(PW1 * C0 * IS3) * s101;  b = (float)(PW1 * IS3 * C1) * s011; }
    else               { a = (float)(PW1 * IS6 * C1) * s111;  b = 0.f; }
    g_WA[idx] = a;
    g_WB[idx] = b;
}

// ---------------------------------------------------------------------------
// Main kernel: one CTA per (n, x, y-half of 64 pixels). 256 threads.
// GEMM: 256 rows (4 g-groups x 64 px) x 48 cols, K=80. Thread tile 8x6.
// ---------------------------------------------------------------------------
__global__ __launch_bounds__(256, 2)
void spinconv_kernel(const float* __restrict__ feat,
                     const float* __restrict__ spin,
                     float* __restrict__ out) {
    extern __shared__ float smem[];
    float* sWA = smem;
    float* sWB = smem + 3840;
    float* sT  = smem + 7680;   // feat tile, later reused for intermediates

    const int b   = blockIdx.x;
    const int n   = b >> 8;
    const int x   = (b >> 1) & 127;
    const int y0  = (b & 1) << 6;
    const int tid = threadIdx.x;

    // ---- load weights into smem ----
    #pragma unroll
    for (int i = tid; i < 3840; i += 256) { sWA[i] = g_WA[i]; sWB[i] = g_WB[i]; }

    // ---- load feat tile (194 pixels x 64 floats), padded rows ----
    const int xm = (x + 127) & 127;
    const int xp = (x + 1) & 127;
    const size_t nbase = (size_t)n * (128 * 128 * 64);
    for (int idx = tid; idx < NTP * 16; idx += 256) {
        int tp = idx >> 4;
        int f  = (idx & 15) << 2;
        int row, yy;
        if (tp < 66)       { row = x;  yy = (y0 + tp + 127) & 127; } // center row, y-halo
        else if (tp < 130) { row = xm; yy = y0 + (tp - 66); }        // x-1
        else               { row = xp; yy = y0 + (tp - 130); }       // x+1
        float4 v = *(const float4*)(feat + nbase + ((size_t)row * 128 + yy) * 64 + f);
        float* dst = sT + tp * TPAD + f;
        dst[0] = v.x; dst[1] = v.y; dst[2] = v.z; dst[3] = v.w;
    }
    __syncthreads();

    // ---- GEMM ----
    const int colg = tid & 7;          // 8 column groups of 6
    const int rowg = tid >> 3;         // 32 row groups of 8
    const int g    = rowg >> 3;        // 0..3 (warp-uniform)
    const int p0   = (rowg & 7) << 3;  // pixel base for this thread
    const int j0   = colg * 6;
    const float* W     = (g == 3) ? sWB : sWA;
    const int    fbase = (g == 3) ? 0 : (16 + g);
    const int    fstep = (g == 3) ? 1 : 3;

    float acc[8][6];
    #pragma unroll
    for (int m = 0; m < 8; m++)
        #pragma unroll
        for (int j = 0; j < 6; j++) acc[m][j] = 0.f;

    #pragma unroll
    for (int tap = 0; tap < 5; tap++) {
        // tile pixel index of tap for pixel p: center=1+p, x-1=66+p, x+1=130+p, y-1=p, y+1=2+p
        const int base = (tap == 0) ? 1 : (tap == 1) ? 66 : (tap == 2) ? 130 : (tap == 3) ? 0 : 2;
        const float* tb = sT + (base + p0) * TPAD + fbase;
        const float* wr = W + tap * (16 * 48) + j0;
        #pragma unroll 4
        for (int c = 0; c < 16; c++) {
            float xi[8];
            #pragma unroll
            for (int m = 0; m < 8; m++) xi[m] = tb[m * TPAD];
            float wv[6];
            #pragma unroll
            for (int j = 0; j < 6; j++) wv[j] = wr[j];
            #pragma unroll
            for (int m = 0; m < 8; m++)
                #pragma unroll
                for (int j = 0; j < 6; j++)
                    acc[m][j] = fmaf(xi[m], wv[j], acc[m][j]);
            tb += fstep;
            wr += 48;
        }
    }
    __syncthreads();   // tile no longer needed; reuse sT for intermediates

    // ---- stash intermediates I[row=g*64+p][48] (pad 49) ----
    #pragma unroll
    for (int m = 0; m < 8; m++) {
        float* dst = sT + ((g << 6) + p0 + m) * IPAD + j0;
        #pragma unroll
        for (int j = 0; j < 6; j++) dst[j] = acc[m][j];
    }
    __syncthreads();

    // ---- epilogue: 4 threads per pixel, each does 4 d's ----
    const int p  = tid >> 2;
    const int d0 = (tid & 3) << 2;
    const size_t q = ((size_t)n * 128 + x) * 128 + (y0 + p);
    const float s0 = spin[q * 3 + 1];
    const float s1 = spin[q * 3 + 2];
    const float s2 = spin[q * 3 + 0];

    const float* I0 = sT + (0 * 64 + p) * IPAD;    // i=0 block
    const float* I1 = sT + (1 * 64 + p) * IPAD;    // i=1
    const float* I2 = sT + (2 * 64 + p) * IPAD;    // i=2
    const float* I3 = sT + (3 * 64 + p) * IPAD;    // x0 block: [a0|b]

    float o0[4], o1[12];
    #pragma unroll
    for (int t = 0; t < 4; t++) {
        const int d = d0 + t;
        const float a0 = I3[d];
        const float bv = I3[16 + d];
        const float h0 = I0[d],      h1 = I1[d],      h2 = I2[d];       // s110
        const float a1 = I0[16 + d], b1 = I1[16 + d], c1 = I2[16 + d];  // s101
        const float t0 = I0[32 + d], t1 = I1[32 + d], t2 = I2[32 + d];  // t

        o0[t] = a0 + h0 * s0 + h1 * s1 + h2 * s2;
        const float cx = t1 * s2 - t2 * s1;
        const float cy = t2 * s0 - t0 * s2;
        const float cz = t0 * s1 - t1 * s0;
        o1[t * 3 + 0] = fmaf(bv, s0, a1) + cx;
        o1[t * 3 + 1] = fmaf(bv, s1, b1) + cy;
        o1[t * 3 + 2] = fmaf(bv, s2, c1) + cz;
    }

    float* op = out + q * 64;
    *(float4*)(op + d0) = make_float4(o0[0], o0[1], o0[2], o0[3]);
    const int ob = 16 + 3 * d0;
    *(float4*)(op + ob + 0) = make_float4(o1[0], o1[1], o1[2],  o1[3]);
    *(float4*)(op + ob + 4) = make_float4(o1[4], o1[5], o1[6],  o1[7]);
    *(float4*)(op + ob + 8) = make_float4(o1[8], o1[9], o1[10], o1[11]);
}

// ---------------------------------------------------------------------------
extern "C" void kernel_launch(void* const* d_in, const int* in_sizes, int n_in,
                              void* d_out, int out_size) {
    const float* feat = (const float*)d_in[0];
    const float* spin = (const float*)d_in[1];
    const float* w000 = (const float*)d_in[2];
    const float* w011 = (const float*)d_in[3];
    const float* w101 = (const float*)d_in[4];
    const float* w110 = (const float*)d_in[5];
    const float* w111 = (const float*)d_in[6];
    float* out = (float*)d_out;

    (void)in_sizes; (void)n_in; (void)out_size;

    cudaFuncSetAttribute(spinconv_kernel,
                         cudaFuncAttributeMaxDynamicSharedMemorySize, SMEM_BYTES);

    prep_weights<<<(80 * 48 + 255) / 256, 256>>>(w000, w011, w101, w110, w111);
    spinconv_kernel<<<8 * 128 * 2, 256, SMEM_BYTES>>>(feat, spin, out);
}